// round 14
// baseline (speedup 1.0000x reference)
#include <cuda_runtime.h>

// SudokuIterate: warp-per-board compute, block-cooperative cp.async staging.
// All global reads (sudoku + rmask, 8 boards = 45.6KB) are issued as aligned
// 16B cp.async into smem before any compute — full MLP with zero register
// cost — then each warp processes its board independently (shfl argmax,
// LDS-fed epilogue). Registers stay low so occupancy recovers to ~62%.
//
// Inputs (metadata order):
//   d_in[0] sudoku          [B,9,9,9] f32   (B*729 elems)
//   d_in[1] recursion_mask  [B,9,9,9] f32
//   d_in[2] recursion_index [B,1,1,1] f32   (B elems)
//   d_in[3] conv_w          [1,9,1,1] f32   (9 elems)
//   d_in[4] conv_b          [1]       f32
// Output: concat(sudoku_out [B*729], recursion_mask_out [B*729], recursion_index+1 [B])

#define KDIM    9
#define CELLS   81
#define ELEMS   729
#define WPB     8                    // warps (= boards) per block
#define THREADS (WPB * 32)
#define SEL     (WPB * ELEMS)        // 5832 floats per array per block
#define NV4     (SEL / 4)            // 1458 float4 per array per block
#define NITER   23                   // ceil(729/32)

// Monotone map fp32 -> uint32 (order-preserving incl. negatives)
__device__ __forceinline__ unsigned int fmap(float f) {
    unsigned int u = __float_as_uint(f);
    return (u & 0x80000000u) ? ~u : (u | 0x80000000u);
}

__device__ __forceinline__ void cp_async16(unsigned int smem_addr, const void* gptr) {
    asm volatile("cp.async.cg.shared.global [%0], [%1], 16;" :: "r"(smem_addr), "l"(gptr));
}

__global__ __launch_bounds__(THREADS, 5)
void sudoku_cpasync_kernel(const float* __restrict__ sud,
                           const float* __restrict__ rmask,
                           const float* __restrict__ rindex,
                           const float* __restrict__ conv_w,
                           const float* __restrict__ conv_b,
                           float* __restrict__ out,
                           int B) {
    __shared__ float sK[SEL];   // sudoku, 8 boards, linear
    __shared__ float sR[SEL];   // recursion_mask, 8 boards, linear

    const int t    = threadIdx.x;
    const int warp = t >> 5;
    const int lane = t & 31;
    const int b0   = blockIdx.x * WPB;
    const int nb   = min(WPB, B - b0);
    const size_t blockbase = (size_t)b0 * ELEMS;

    // ---- Stage ALL global reads via cp.async (16B, aligned at block scope) ----
    if (nb == WPB) {
        const char* gK = (const char*)(sud   + blockbase);
        const char* gR = (const char*)(rmask + blockbase);
        unsigned int aK = (unsigned int)__cvta_generic_to_shared(sK);
        unsigned int aR = (unsigned int)__cvta_generic_to_shared(sR);
        #pragma unroll
        for (int i = 0; i < 6; i++) {
            int v = t + i * THREADS;
            if (v < NV4) {
                cp_async16(aK + v * 16, gK + v * 16);
                cp_async16(aR + v * 16, gR + v * 16);
            }
        }
        asm volatile("cp.async.commit_group;");
        asm volatile("cp.async.wait_group 0;");
    } else {
        // Tail fallback (scalar; not hit for B=32768)
        const int tot = nb * ELEMS;
        for (int e = t; e < tot; e += THREADS) {
            sK[e] = sud[blockbase + e];
            sR[e] = rmask[blockbase + e];
        }
    }
    __syncthreads();

    const int b = b0 + warp;
    if (b >= B) return;  // no barriers after this point

    const float cb = conv_b[0];
    float w[KDIM];
    #pragma unroll
    for (int c = 0; c < KDIM; c++) w[c] = __ldg(conv_w + c);
    const float ri = __ldg(rindex + b);

    const float* __restrict__ sw = sK + warp * ELEMS;
    const float* __restrict__ rw = sR + warp * ELEMS;

    // ---- Per-cell score; warp argmax with first-index tie-break ----
    unsigned long long key = 0ull;
    #pragma unroll
    for (int it = 0; it < 3; it++) {
        int cell = lane + 32 * it;
        if (cell < CELLS) {
            float cnt = cb;
            #pragma unroll
            for (int c = 0; c < KDIM; c++) cnt = fmaf(sw[c * CELLS + cell], w[c], cnt);
            float nic   = fmaxf(cnt - 1.0f, 0.0f);
            float m0    = fminf(fmaxf(1.0f - fabsf(nic), 0.0f), 1.0f) * (-(float)KDIM);
            float score = m0 - nic;
            unsigned long long k =
                ((unsigned long long)fmap(score) << 7) | (unsigned long long)(127 - cell);
            if (k > key) key = k;
        }
    }
    #pragma unroll
    for (int off = 16; off > 0; off >>= 1) {
        unsigned long long o = __shfl_xor_sync(0xffffffffu, key, off);
        if (o > key) key = o;
    }
    const int cell_star = 127 - (int)(key & 127ull);

    // ---- Channel argmax at chosen cell (broadcast smem reads) ----
    float mval = sw[cell_star];
    int   midx = 0;
    #pragma unroll
    for (int c = 1; c < KDIM; c++) {
        float v = sw[c * CELLS + cell_star];
        if (v > mval) { mval = v; midx = c; }
    }
    const float cm_star = fminf(fmaxf(fmaf(mval, w[midx], cb), 0.0f), 1.0f);
    const float cbclip  = fminf(fmaxf(cb, 0.0f), 1.0f);

    const size_t N    = (size_t)B * ELEMS;
    const size_t base = (size_t)b * ELEMS;
    float* __restrict__ out_sud = out + base;
    float* __restrict__ out_rm  = out + N + base;

    // ---- Elementwise epilogue: LDS-fed compute + stores ----
    #pragma unroll
    for (int i = 0; i < NITER; i++) {
        int idx = lane + 32 * i;
        if (idx < ELEMS) {
            int   c    = idx / CELLS;
            int   cell = idx - c * CELLS;
            float sv   = sw[idx];
            float rv   = rw[idx];
            bool  star = (cell == cell_star);
            float ov   = (star && c == midx) ? mval : 0.0f;
            float cm   = star ? cm_star : cbclip;
            float orm  = sv * cm * (1.0f - ov);
            out_sud[idx] = sv * (1.0f - orm);
            out_rm[idx]  = fmaxf(rv, fmaxf(ri * orm, (ri - 1.0f) * ov));
        }
    }
    if (lane == 0) out[2 * N + b] = ri + 1.0f;
}

extern "C" void kernel_launch(void* const* d_in, const int* in_sizes, int n_in,
                              void* d_out, int out_size) {
    const float* sud    = (const float*)d_in[0];
    const float* rmask  = (const float*)d_in[1];
    const float* rindex = (const float*)d_in[2];
    const float* conv_w = (const float*)d_in[3];
    const float* conv_b = (const float*)d_in[4];
    float* out = (float*)d_out;
    int B = in_sizes[2];  // number of boards (recursion_index element count)

    int grid = (B + WPB - 1) / WPB;
    sudoku_cpasync_kernel<<<grid, THREADS>>>(sud, rmask, rindex, conv_w, conv_b, out, B);
}